// round 3
// baseline (speedup 1.0000x reference)
#include <cuda_runtime.h>

// KGAT neighbor attention, algebraically folded.
//
// Key identity: there is no activation between fc1 and fc2, so
//   logits = concat @ (W1 @ W2) + (b1 . W2 + b2)
// Let v = W1 @ W2  (384 floats), split v = [v1 | v2 | v3] (128 each), and
// c = b1 . W2 + b2. Then per (b,n) pair and neighbor k:
//   logit_k = e . v1 + ne_k . v2 + nr_k . v3 + c
// Softmax over K=5, then out = [e, sum_k att_k * ne_k].
//
// Kernel 1 (tiny): fold W1,W2,b1,b2 -> g_v[0..383], g_v[384]=c.
// Kernel 2 (streaming, HBM-bound): one warp per (b,n) pair.

#define D        128
#define K        5
#define WARPS_PER_BLOCK 8
#define THREADS  (WARPS_PER_BLOCK * 32)

__device__ __align__(16) float g_v[388];   // 384 folded weights + c (padded)

__global__ void fold_mlp_kernel(const float* __restrict__ W1,
                                const float* __restrict__ b1,
                                const float* __restrict__ W2,
                                const float* __restrict__ b2) {
    int f = blockIdx.x * blockDim.x + threadIdx.x;
    if (f < 384) {
        // W1 is (384, 128) row-major, W2 is (128, 1)
        float s = 0.0f;
        #pragma unroll 8
        for (int a = 0; a < 128; a++)
            s = fmaf(W1[f * 128 + a], W2[a], s);
        g_v[f] = s;
    } else if (f == 384) {
        float s = b2[0];
        for (int a = 0; a < 128; a++)
            s = fmaf(b1[a], W2[a], s);
        g_v[384] = s;
    }
}

__device__ __forceinline__ float warp_sum(float x) {
    #pragma unroll
    for (int o = 16; o > 0; o >>= 1)
        x += __shfl_xor_sync(0xffffffffu, x, o);
    return x;
}

__device__ __forceinline__ float dot4(float4 a, float4 b) {
    return fmaf(a.x, b.x, fmaf(a.y, b.y, fmaf(a.z, b.z, a.w * b.w)));
}

__global__ void __launch_bounds__(THREADS)
kgat_kernel(const float* __restrict__ ent,     // [P, 128]
            const float* __restrict__ ne,      // [P, K, 128]
            const float* __restrict__ nr,      // [P, K, 128]
            float* __restrict__ out,           // [P, 256]
            int total_pairs)
{
    const int warp = (blockIdx.x * blockDim.x + threadIdx.x) >> 5;
    const int lane = threadIdx.x & 31;
    if (warp >= total_pairs) return;

    // Folded weight vectors (L1/L2 resident after first touch)
    const float4* vp = reinterpret_cast<const float4*>(g_v);
    const float4 v1 = __ldg(vp + lane);        // v[0:128]
    const float4 v2 = __ldg(vp + 32 + lane);   // v[128:256]
    const float4 v3 = __ldg(vp + 64 + lane);   // v[256:384]
    const float  c  = __ldg(&g_v[384]);

    // Entity embedding: 128 floats, lane owns 4 (float4, coalesced)
    const float4* ep = reinterpret_cast<const float4*>(ent + (size_t)warp * D);
    const float4 e4 = __ldg(ep + lane);
    const float d1 = warp_sum(dot4(e4, v1));

    // Neighbor embeddings: load once, keep ne in registers for the weighted sum
    const float4* nep = reinterpret_cast<const float4*>(ne + (size_t)warp * (K * D));
    const float4* nrp = reinterpret_cast<const float4*>(nr + (size_t)warp * (K * D));

    float4 nek[K];
    float  logit[K];
    #pragma unroll
    for (int k = 0; k < K; k++) {
        nek[k]    = __ldg(nep + k * 32 + lane);
        float4 r4 = __ldg(nrp + k * 32 + lane);
        logit[k]  = dot4(nek[k], v2) + dot4(r4, v3);
    }
    #pragma unroll
    for (int k = 0; k < K; k++)
        logit[k] = warp_sum(logit[k]) + d1 + c;   // every lane has all K logits

    // Softmax over K=5 (fp32)
    float m = logit[0];
    #pragma unroll
    for (int k = 1; k < K; k++) m = fmaxf(m, logit[k]);
    float ex[K], sum = 0.0f;
    #pragma unroll
    for (int k = 0; k < K; k++) { ex[k] = __expf(logit[k] - m); sum += ex[k]; }
    const float inv = 1.0f / sum;

    // Weighted sum of neighbor entity embeddings
    float4 acc = make_float4(0.f, 0.f, 0.f, 0.f);
    #pragma unroll
    for (int k = 0; k < K; k++) {
        const float a = ex[k] * inv;
        acc.x = fmaf(a, nek[k].x, acc.x);
        acc.y = fmaf(a, nek[k].y, acc.y);
        acc.z = fmaf(a, nek[k].z, acc.z);
        acc.w = fmaf(a, nek[k].w, acc.w);
    }

    // Output: [e | neigh_att], 256 floats per pair, float4 stores
    float4* op = reinterpret_cast<float4*>(out + (size_t)warp * (2 * D));
    op[lane]      = e4;
    op[32 + lane] = acc;
}

extern "C" void kernel_launch(void* const* d_in, const int* in_sizes, int n_in,
                              void* d_out, int out_size) {
    const float* ent = (const float*)d_in[0];   // entity_embedding   [B,N,128]
    const float* ne  = (const float*)d_in[1];   // neigh_entity       [B,N,5,128]
    const float* nr  = (const float*)d_in[2];   // neigh_relation     [B,N,5,128]
    const float* W1  = (const float*)d_in[3];   // [384,128]
    const float* b1  = (const float*)d_in[4];   // [128]
    const float* W2  = (const float*)d_in[5];   // [128,1]
    const float* b2  = (const float*)d_in[6];   // [1]
    float* out = (float*)d_out;

    const int total_pairs = in_sizes[0] / D;    // B*N

    fold_mlp_kernel<<<1, 512>>>(W1, b1, W2, b2);

    const int blocks = (total_pairs + WARPS_PER_BLOCK - 1) / WARPS_PER_BLOCK;
    kgat_kernel<<<blocks, THREADS>>>(ent, ne, nr, out, total_pairs);
}

// round 4
// speedup vs baseline: 1.4405x; 1.4405x over previous
#include <cuda_runtime.h>

// KGAT neighbor attention, algebraically folded.
//
// Key identity: there is no activation between fc1 and fc2, so
//   logits = concat @ (W1 @ W2) + (b1 . W2 + b2)
// Let v = W1 @ W2  (384 floats), split v = [v1 | v2 | v3] (128 each), and
// c = b1 . W2 + b2. Then per (b,n) pair and neighbor k:
//   logit_k = e . v1 + ne_k . v2 + nr_k . v3 + c
// Softmax over K=5, then out = [e, sum_k att_k * ne_k].
//
// Kernel 1: warp-per-output fold (coalesced, one wave, ~2 us).
// Kernel 2: streaming, HBM-bound: one warp per (b,n) pair (at LTS ceiling).

#define D        128
#define K        5
#define WARPS_PER_BLOCK 8
#define THREADS  (WARPS_PER_BLOCK * 32)

__device__ __align__(16) float g_v[388];   // 384 folded weights + c (padded)

__device__ __forceinline__ float warp_sum(float x) {
    #pragma unroll
    for (int o = 16; o > 0; o >>= 1)
        x += __shfl_xor_sync(0xffffffffu, x, o);
    return x;
}

__device__ __forceinline__ float dot4(float4 a, float4 b) {
    return fmaf(a.x, b.x, fmaf(a.y, b.y, fmaf(a.z, b.z, a.w * b.w)));
}

// One warp per output element f (0..383): coalesced float4 row load of W1,
// warp-shuffle reduction. Warp 384 computes the folded bias c.
__global__ void __launch_bounds__(THREADS)
fold_mlp_kernel(const float* __restrict__ W1,   // [384, 128] row-major
                const float* __restrict__ b1,   // [128]
                const float* __restrict__ W2,   // [128, 1]
                const float* __restrict__ b2)   // [1]
{
    const int warp = (blockIdx.x * blockDim.x + threadIdx.x) >> 5;
    const int lane = threadIdx.x & 31;

    const float4 w2 = __ldg(reinterpret_cast<const float4*>(W2) + lane);

    if (warp < 384) {
        const float4 a = __ldg(reinterpret_cast<const float4*>(W1 + (size_t)warp * 128) + lane);
        const float s = warp_sum(dot4(a, w2));
        if (lane == 0) g_v[warp] = s;
    } else if (warp == 384) {
        const float4 bb = __ldg(reinterpret_cast<const float4*>(b1) + lane);
        const float s = warp_sum(dot4(bb, w2));
        if (lane == 0) g_v[384] = s + __ldg(b2);
    }
}

__global__ void __launch_bounds__(THREADS)
kgat_kernel(const float* __restrict__ ent,     // [P, 128]
            const float* __restrict__ ne,      // [P, K, 128]
            const float* __restrict__ nr,      // [P, K, 128]
            float* __restrict__ out,           // [P, 256]
            int total_pairs)
{
    const int warp = (blockIdx.x * blockDim.x + threadIdx.x) >> 5;
    const int lane = threadIdx.x & 31;
    if (warp >= total_pairs) return;

    // Folded weight vectors (L1/L2 resident after first touch)
    const float4* vp = reinterpret_cast<const float4*>(g_v);
    const float4 v1 = __ldg(vp + lane);        // v[0:128]
    const float4 v2 = __ldg(vp + 32 + lane);   // v[128:256]
    const float4 v3 = __ldg(vp + 64 + lane);   // v[256:384]
    const float  c  = __ldg(&g_v[384]);

    // Entity embedding: 128 floats, lane owns 4 (float4, coalesced)
    const float4* ep = reinterpret_cast<const float4*>(ent + (size_t)warp * D);
    const float4 e4 = __ldg(ep + lane);
    const float d1 = warp_sum(dot4(e4, v1));

    // Neighbor embeddings: load once, keep ne in registers for the weighted sum
    const float4* nep = reinterpret_cast<const float4*>(ne + (size_t)warp * (K * D));
    const float4* nrp = reinterpret_cast<const float4*>(nr + (size_t)warp * (K * D));

    float4 nek[K];
    float  logit[K];
    #pragma unroll
    for (int k = 0; k < K; k++) {
        nek[k]    = __ldg(nep + k * 32 + lane);
        float4 r4 = __ldg(nrp + k * 32 + lane);
        logit[k]  = dot4(nek[k], v2) + dot4(r4, v3);
    }
    #pragma unroll
    for (int k = 0; k < K; k++)
        logit[k] = warp_sum(logit[k]) + d1 + c;   // every lane has all K logits

    // Softmax over K=5 (fp32)
    float m = logit[0];
    #pragma unroll
    for (int k = 1; k < K; k++) m = fmaxf(m, logit[k]);
    float ex[K], sum = 0.0f;
    #pragma unroll
    for (int k = 0; k < K; k++) { ex[k] = __expf(logit[k] - m); sum += ex[k]; }
    const float inv = 1.0f / sum;

    // Weighted sum of neighbor entity embeddings
    float4 acc = make_float4(0.f, 0.f, 0.f, 0.f);
    #pragma unroll
    for (int k = 0; k < K; k++) {
        const float a = ex[k] * inv;
        acc.x = fmaf(a, nek[k].x, acc.x);
        acc.y = fmaf(a, nek[k].y, acc.y);
        acc.z = fmaf(a, nek[k].z, acc.z);
        acc.w = fmaf(a, nek[k].w, acc.w);
    }

    // Output: [e | neigh_att], 256 floats per pair, float4 stores
    float4* op = reinterpret_cast<float4*>(out + (size_t)warp * (2 * D));
    op[lane]      = e4;
    op[32 + lane] = acc;
}

extern "C" void kernel_launch(void* const* d_in, const int* in_sizes, int n_in,
                              void* d_out, int out_size) {
    const float* ent = (const float*)d_in[0];   // entity_embedding   [B,N,128]
    const float* ne  = (const float*)d_in[1];   // neigh_entity       [B,N,5,128]
    const float* nr  = (const float*)d_in[2];   // neigh_relation     [B,N,5,128]
    const float* W1  = (const float*)d_in[3];   // [384,128]
    const float* b1  = (const float*)d_in[4];   // [128]
    const float* W2  = (const float*)d_in[5];   // [128,1]
    const float* b2  = (const float*)d_in[6];   // [1]
    float* out = (float*)d_out;

    const int total_pairs = in_sizes[0] / D;    // B*N

    // 385 warps needed -> 49 blocks of 8 warps
    fold_mlp_kernel<<<49, THREADS>>>(W1, b1, W2, b2);

    const int blocks = (total_pairs + WARPS_PER_BLOCK - 1) / WARPS_PER_BLOCK;
    kgat_kernel<<<blocks, THREADS>>>(ent, ne, nr, out, total_pairs);
}

// round 5
// speedup vs baseline: 1.4920x; 1.0357x over previous
#include <cuda_runtime.h>

// KGAT neighbor attention, algebraically folded.
//
// Key identity: no activation between fc1 and fc2, so
//   logits = concat @ (W1 @ W2) + (b1 . W2 + b2)
// v = W1 @ W2 (384 floats) = [v1 | v2 | v3], c = b1 . W2 + b2.
// Per (b,n) pair, neighbor k: logit_k = e.v1 + ne_k.v2 + nr_k.v3 + c
// Softmax over K=5, out = [e, sum_k att_k * ne_k].
//
// Kernel 1: warp-per-output fold (coalesced, one wave).
// Kernel 2: streaming warp-per-pair, evict-first cache policy (HBM-bound).

#define D        128
#define K        5
#define WARPS_PER_BLOCK 8
#define THREADS  (WARPS_PER_BLOCK * 32)

__device__ __align__(16) float g_v[388];   // 384 folded weights + c (padded)

__device__ __forceinline__ float warp_sum(float x) {
    #pragma unroll
    for (int o = 16; o > 0; o >>= 1)
        x += __shfl_xor_sync(0xffffffffu, x, o);
    return x;
}

__device__ __forceinline__ float dot4(float4 a, float4 b) {
    return fmaf(a.x, b.x, fmaf(a.y, b.y, fmaf(a.z, b.z, a.w * b.w)));
}

// One warp per output element f (0..383): coalesced float4 row load of W1,
// warp-shuffle reduction. Warp 384 computes the folded bias c.
__global__ void __launch_bounds__(THREADS)
fold_mlp_kernel(const float* __restrict__ W1,   // [384, 128] row-major
                const float* __restrict__ b1,   // [128]
                const float* __restrict__ W2,   // [128, 1]
                const float* __restrict__ b2)   // [1]
{
    const int warp = (blockIdx.x * blockDim.x + threadIdx.x) >> 5;
    const int lane = threadIdx.x & 31;

    const float4 w2 = __ldg(reinterpret_cast<const float4*>(W2) + lane);

    if (warp < 384) {
        const float4 a = __ldg(reinterpret_cast<const float4*>(W1 + (size_t)warp * 128) + lane);
        const float s = warp_sum(dot4(a, w2));
        if (lane == 0) g_v[warp] = s;
    } else if (warp == 384) {
        const float4 bb = __ldg(reinterpret_cast<const float4*>(b1) + lane);
        const float s = warp_sum(dot4(bb, w2));
        if (lane == 0) g_v[384] = s + __ldg(b2);
    }
}

__global__ void __launch_bounds__(THREADS)
kgat_kernel(const float* __restrict__ ent,     // [P, 128]
            const float* __restrict__ ne,      // [P, K, 128]
            const float* __restrict__ nr,      // [P, K, 128]
            float* __restrict__ out,           // [P, 256]
            int total_pairs)
{
    const int warp = (blockIdx.x * blockDim.x + threadIdx.x) >> 5;
    const int lane = threadIdx.x & 31;
    if (warp >= total_pairs) return;

    // Folded weight vectors (cached: heavily reused across all warps)
    const float4* vp = reinterpret_cast<const float4*>(g_v);
    const float4 v1 = __ldg(vp + lane);        // v[0:128]
    const float4 v2 = __ldg(vp + 32 + lane);   // v[128:256]
    const float4 v3 = __ldg(vp + 64 + lane);   // v[256:384]
    const float  c  = __ldg(&g_v[384]);

    // Streaming data: zero reuse -> evict-first (.cs) to keep L1/L2 clean.
    const float4* ep  = reinterpret_cast<const float4*>(ent + (size_t)warp * D);
    const float4* nep = reinterpret_cast<const float4*>(ne + (size_t)warp * (K * D));
    const float4* nrp = reinterpret_cast<const float4*>(nr + (size_t)warp * (K * D));

    const float4 e4 = __ldcs(ep + lane);

    float4 nek[K];
    float4 nrk[K];
    #pragma unroll
    for (int k = 0; k < K; k++) {
        nek[k] = __ldcs(nep + k * 32 + lane);
        nrk[k] = __ldcs(nrp + k * 32 + lane);
    }

    // Per-lane partial logits: e.v1 folded into each (one fewer reduction)
    const float ev1 = dot4(e4, v1);
    float logit[K];
    #pragma unroll
    for (int k = 0; k < K; k++)
        logit[k] = ev1 + dot4(nek[k], v2) + dot4(nrk[k], v3);
    #pragma unroll
    for (int k = 0; k < K; k++)
        logit[k] = warp_sum(logit[k]) + c;   // every lane has all K logits

    // Softmax over K=5 (fp32)
    float m = logit[0];
    #pragma unroll
    for (int k = 1; k < K; k++) m = fmaxf(m, logit[k]);
    float ex[K], sum = 0.0f;
    #pragma unroll
    for (int k = 0; k < K; k++) { ex[k] = __expf(logit[k] - m); sum += ex[k]; }
    const float inv = 1.0f / sum;

    // Weighted sum of neighbor entity embeddings
    float4 acc = make_float4(0.f, 0.f, 0.f, 0.f);
    #pragma unroll
    for (int k = 0; k < K; k++) {
        const float a = ex[k] * inv;
        acc.x = fmaf(a, nek[k].x, acc.x);
        acc.y = fmaf(a, nek[k].y, acc.y);
        acc.z = fmaf(a, nek[k].z, acc.z);
        acc.w = fmaf(a, nek[k].w, acc.w);
    }

    // Output: [e | neigh_att], 256 floats per pair; write-once -> evict-first
    float4* op = reinterpret_cast<float4*>(out + (size_t)warp * (2 * D));
    __stcs(op + lane, e4);
    __stcs(op + 32 + lane, acc);
}

extern "C" void kernel_launch(void* const* d_in, const int* in_sizes, int n_in,
                              void* d_out, int out_size) {
    const float* ent = (const float*)d_in[0];   // entity_embedding   [B,N,128]
    const float* ne  = (const float*)d_in[1];   // neigh_entity       [B,N,5,128]
    const float* nr  = (const float*)d_in[2];   // neigh_relation     [B,N,5,128]
    const float* W1  = (const float*)d_in[3];   // [384,128]
    const float* b1  = (const float*)d_in[4];   // [128]
    const float* W2  = (const float*)d_in[5];   // [128,1]
    const float* b2  = (const float*)d_in[6];   // [1]
    float* out = (float*)d_out;

    const int total_pairs = in_sizes[0] / D;    // B*N

    // 385 warps needed -> 49 blocks of 8 warps
    fold_mlp_kernel<<<49, THREADS>>>(W1, b1, W2, b2);

    const int blocks = (total_pairs + WARPS_PER_BLOCK - 1) / WARPS_PER_BLOCK;
    kgat_kernel<<<blocks, THREADS>>>(ent, ne, nr, out, total_pairs);
}